// round 4
// baseline (speedup 1.0000x reference)
#include <cuda_runtime.h>

#define NN 40000
#define NE 640000
#define DD 128
#define LL 3

// ---------------- scratch (static __device__, no allocation) ----------------
__device__ __align__(256) float g_A[NN * DD];    // x @ psi_top + psi_b (by dst)
__device__ __align__(256) float g_B[NN * DD];    // x @ psi_bot        (by src)
__device__ __align__(256) float g_agg[NN * DD];  // scatter-mean result
__device__ __align__(256) float g_xa[NN * DD];   // x double buffer 0
__device__ __align__(256) float g_xb[NN * DD];   // x double buffer 1
__device__ float g_invdeg[NN];
__device__ int   g_deg[NN];
__device__ int   g_rowptr[NN + 1];
__device__ int   g_cursor[NN];
__device__ int   g_esrc[NE];        // CSR: source node per edge, grouped by dst

// device-side buffer resolution (avoids cudaGetSymbolAddress on host)
__device__ __forceinline__ float* resolve_buf(int id) {
    switch (id) {
        case 0: return g_A;
        case 1: return g_B;
        case 2: return g_agg;
        case 3: return g_xa;
        case 4: return g_xb;
        default: return nullptr;
    }
}

// ---------------- CSR build ----------------
__global__ void zero_deg_kernel() {
    int i = blockIdx.x * blockDim.x + threadIdx.x;
    if (i < NN) g_deg[i] = 0;
}

// edge_index arrives as int32: row 0 (src) at [0,NE), row 1 (dst) at [NE,2NE)
__global__ void hist_kernel(const int* __restrict__ ei) {
    int e = blockIdx.x * blockDim.x + threadIdx.x;
    if (e < NE) {
        unsigned d = (unsigned)ei[NE + e];
        if (d < NN) atomicAdd(&g_deg[d], 1);
    }
}

// single-block exclusive scan over g_deg -> rowptr/cursor, plus inv_deg
__global__ void scan_kernel() {
    __shared__ int sh[1024];
    __shared__ int carry_s;
    int tid = threadIdx.x;
    if (tid == 0) carry_s = 0;
    __syncthreads();
    for (int base = 0; base < NN; base += 1024) {
        int i = base + tid;
        int v = (i < NN) ? g_deg[i] : 0;
        sh[tid] = v;
        __syncthreads();
        #pragma unroll
        for (int off = 1; off < 1024; off <<= 1) {
            int t = (tid >= off) ? sh[tid - off] : 0;
            __syncthreads();
            sh[tid] += t;
            __syncthreads();
        }
        int incl = sh[tid];
        int carry = carry_s;
        if (i < NN) {
            int excl = carry + incl - v;
            g_rowptr[i] = excl;
            g_cursor[i] = excl;
            g_invdeg[i] = 1.0f / (float)(v > 1 ? v : 1);
        }
        __syncthreads();
        if (tid == 1023) carry_s = carry + sh[1023];
        __syncthreads();
    }
    if (tid == 0) g_rowptr[NN] = carry_s;
}

__global__ void fill_kernel(const int* __restrict__ ei) {
    int e = blockIdx.x * blockDim.x + threadIdx.x;
    if (e < NE) {
        unsigned dst = (unsigned)ei[NE + e];
        unsigned src = (unsigned)ei[e];
        if (dst < NN && src < NN) {
            int pos = atomicAdd(&g_cursor[dst], 1);
            g_esrc[pos] = (int)src;
        }
    }
}

// ---------------- edge aggregation: one warp per node ----------------
// agg[i] = inv_deg[i] * sum_{e in seg(i)} relu(A[i] + B[src_e])
__global__ void agg_kernel() {
    int gt = blockIdx.x * blockDim.x + threadIdx.x;
    int node = gt >> 5;
    int lane = threadIdx.x & 31;
    if (node >= NN) return;
    int c = lane << 2;
    const float4 a = *(const float4*)&g_A[node * DD + c];
    float4 acc = make_float4(0.f, 0.f, 0.f, 0.f);
    int e0 = g_rowptr[node];
    int e1 = g_rowptr[node + 1];
    for (int e = e0; e < e1; ++e) {
        int s = g_esrc[e];
        float4 b = *(const float4*)&g_B[s * DD + c];
        acc.x += fmaxf(a.x + b.x, 0.f);
        acc.y += fmaxf(a.y + b.y, 0.f);
        acc.z += fmaxf(a.z + b.z, 0.f);
        acc.w += fmaxf(a.w + b.w, 0.f);
    }
    float id = g_invdeg[node];
    float4 o = make_float4(acc.x * id, acc.y * id, acc.z * id, acc.w * id);
    *(float4*)&g_agg[node * DD + c] = o;
}

// ---------------- GEMM: out[m,:] = f(X1@W1 (+ X2@W2) + bias) (+ res) -------
// X: [M,128] row-major, W: [128,128] row-major. BM=128, BN=128, KB=32,
// 256 threads, 8x8 microtile per thread. Buffers selected by id (or external
// pointer when id < 0).
template <bool HAS2, bool RELU, bool RES, bool HASBIAS>
__global__ void __launch_bounds__(256, 2) gemm_kernel(
    const float* __restrict__ Xext, const float* __restrict__ W1,
    const float* __restrict__ W2, const float* __restrict__ bias,
    float* __restrict__ OutExt,
    int x1_id, int x2_id, int res_id, int out_id) {
    __shared__ float XsT[32][132];   // [k][m], padded for conflict-free
    __shared__ float Ws[32][128];    // [k][n]

    const float* X1 = (x1_id < 0) ? Xext : resolve_buf(x1_id);
    const float* X2 = HAS2 ? resolve_buf(x2_id) : nullptr;
    const float* res = RES ? ((res_id < 0) ? Xext : resolve_buf(res_id)) : nullptr;
    float* out = (out_id < 0) ? OutExt : resolve_buf(out_id);

    int tid = threadIdx.x;
    int m0 = blockIdx.x * 128;
    int tm = (tid >> 4) << 3;        // 0..120 step 8
    int tn = (tid & 15) << 3;        // 0..120 step 8

    float acc[8][8];
    #pragma unroll
    for (int i = 0; i < 8; i++)
        #pragma unroll
        for (int j = 0; j < 8; j++) acc[i][j] = 0.f;

    int nsrc = HAS2 ? 2 : 1;
    for (int si = 0; si < nsrc; si++) {
        const float* X = (HAS2 && si == 1) ? X2 : X1;
        const float* W = (HAS2 && si == 1) ? W2 : W1;
        for (int k0 = 0; k0 < 128; k0 += 32) {
            __syncthreads();
            // X tile -> XsT (transposed)
            #pragma unroll
            for (int i = 0; i < 4; i++) {
                int f = tid + i * 256;          // 0..1023
                int row = f >> 3;               // 0..127
                int kq = (f & 7) << 2;          // 0..28 step 4
                float4 v = make_float4(0.f, 0.f, 0.f, 0.f);
                int m = m0 + row;
                if (m < NN) v = *(const float4*)&X[m * 128 + k0 + kq];
                XsT[kq + 0][row] = v.x;
                XsT[kq + 1][row] = v.y;
                XsT[kq + 2][row] = v.z;
                XsT[kq + 3][row] = v.w;
            }
            // W tile
            #pragma unroll
            for (int i = 0; i < 4; i++) {
                int f = tid + i * 256;
                int kr = f >> 5;                // 0..31
                int col = (f & 31) << 2;        // 0..124 step 4
                *(float4*)&Ws[kr][col] = *(const float4*)&W[(k0 + kr) * 128 + col];
            }
            __syncthreads();
            #pragma unroll
            for (int kk = 0; kk < 32; kk++) {
                float a[8], b[8];
                float4 a0 = *(const float4*)&XsT[kk][tm];
                float4 a1 = *(const float4*)&XsT[kk][tm + 4];
                float4 b0 = *(const float4*)&Ws[kk][tn];
                float4 b1 = *(const float4*)&Ws[kk][tn + 4];
                a[0] = a0.x; a[1] = a0.y; a[2] = a0.z; a[3] = a0.w;
                a[4] = a1.x; a[5] = a1.y; a[6] = a1.z; a[7] = a1.w;
                b[0] = b0.x; b[1] = b0.y; b[2] = b0.z; b[3] = b0.w;
                b[4] = b1.x; b[5] = b1.y; b[6] = b1.z; b[7] = b1.w;
                #pragma unroll
                for (int i = 0; i < 8; i++)
                    #pragma unroll
                    for (int j = 0; j < 8; j++) acc[i][j] += a[i] * b[j];
            }
        }
    }

    float bv[8];
    if (HASBIAS) {
        #pragma unroll
        for (int j = 0; j < 8; j++) bv[j] = bias[tn + j];
    }
    #pragma unroll
    for (int i = 0; i < 8; i++) {
        int m = m0 + tm + i;
        if (m >= NN) continue;
        float c[8];
        #pragma unroll
        for (int j = 0; j < 8; j++) {
            float v = acc[i][j];
            if (HASBIAS) v += bv[j];
            if (RELU) v = fmaxf(v, 0.f);
            c[j] = v;
        }
        if (RES) {
            float4 r0 = *(const float4*)&res[m * 128 + tn];
            float4 r1 = *(const float4*)&res[m * 128 + tn + 4];
            c[0] += r0.x; c[1] += r0.y; c[2] += r0.z; c[3] += r0.w;
            c[4] += r1.x; c[5] += r1.y; c[6] += r1.z; c[7] += r1.w;
        }
        *(float4*)&out[m * 128 + tn]     = make_float4(c[0], c[1], c[2], c[3]);
        *(float4*)&out[m * 128 + tn + 4] = make_float4(c[4], c[5], c[6], c[7]);
    }
}

// ---------------- launch ----------------
extern "C" void kernel_launch(void* const* d_in, const int* in_sizes, int n_in,
                              void* d_out, int out_size) {
    const float* x     = (const float*)d_in[0];
    const int*   ei    = (const int*)d_in[1];     // int64 -> int32 by harness
    const float* psi_w = (const float*)d_in[2];
    const float* psi_b = (const float*)d_in[3];
    const float* phi_w = (const float*)d_in[4];
    const float* phi_b = (const float*)d_in[5];
    const float* dp_w  = (const float*)d_in[6];
    const float* dp_b  = (const float*)d_in[7];
    float* out = (float*)d_out;

    // CSR build (per call; deterministic result regardless of atomic order
    // up to within-segment permutation, which sums identically)
    zero_deg_kernel<<<(NN + 255) / 256, 256>>>();
    hist_kernel<<<(NE + 255) / 256, 256>>>(ei);
    scan_kernel<<<1, 1024>>>();
    fill_kernel<<<(NE + 255) / 256, 256>>>(ei);

    const int GB = (NN + 127) / 128;          // 313 blocks
    const int AGG_BLOCKS = (NN * 32 + 255) / 256;

    // buffer ids: 0=g_A 1=g_B 2=g_agg 3=g_xa 4=g_xb, -1=external
    int xin_id = -1;                 // layer-0 input is external x
    for (int l = 0; l < LL; l++) {
        const float* psiT = psi_w + (size_t)l * 256 * 128;           // top half
        const float* psiB = psiT + 128 * 128;                        // bottom half
        // A = x @ psi_top + psi_b ; B = x @ psi_bot
        gemm_kernel<false, false, false, true><<<GB, 256>>>(
            x, psiT, nullptr, psi_b + (size_t)l * 128, nullptr,
            xin_id, -1, -1, 0);
        gemm_kernel<false, false, false, false><<<GB, 256>>>(
            x, psiB, nullptr, nullptr, nullptr,
            xin_id, -1, -1, 1);
        // agg = scatter-mean(relu(A[dst] + B[src]))
        agg_kernel<<<AGG_BLOCKS, 256>>>();
        // x = relu(x @ phi_top + agg @ phi_bot + phi_b) + x
        const float* phiT = phi_w + (size_t)l * 256 * 128;
        const float* phiB = phiT + 128 * 128;
        int xout_id = 3 + (l & 1);
        gemm_kernel<true, true, true, true><<<GB, 256>>>(
            x, phiT, phiB, phi_b + (size_t)l * 128, nullptr,
            xin_id, 2, xin_id, xout_id);
        xin_id = xout_id;
    }
    // out = x @ dp_w + dp_b
    gemm_kernel<false, false, false, true><<<GB, 256>>>(
        x, dp_w, nullptr, dp_b, out,
        xin_id, -1, -1, -1);
}

// round 5
// speedup vs baseline: 1.7065x; 1.7065x over previous
#include <cuda_runtime.h>
#include <cstdint>

#define NN 40000
#define NE 640000
#define DD 128
#define LL 3

// ---------------- scratch (static __device__, no allocation) ----------------
__device__ __align__(256) float g_A[NN * DD];    // x @ psi_top + psi_b (by dst)
__device__ __align__(256) float g_B[NN * DD];    // x @ psi_bot        (by src)
__device__ __align__(256) float g_agg[NN * DD];  // scatter-mean result
__device__ __align__(256) float g_xa[NN * DD];   // x double buffer 0
__device__ __align__(256) float g_xb[NN * DD];   // x double buffer 1
__device__ float g_invdeg[NN];
__device__ int   g_deg[NN];
__device__ int   g_rowptr[NN + 1];
__device__ int   g_cursor[NN];
__device__ int   g_esrc[NE];        // CSR: source node per edge, grouped by dst

__device__ __forceinline__ float* resolve_buf(int id) {
    switch (id) {
        case 0: return g_A;
        case 1: return g_B;
        case 2: return g_agg;
        case 3: return g_xa;
        case 4: return g_xb;
        default: return nullptr;
    }
}

__device__ __forceinline__ uint32_t f2tf32(float f) {
    uint32_t u;
    asm("cvt.rna.tf32.f32 %0, %1;" : "=r"(u) : "f"(f));
    return u;
}

// ---------------- CSR build ----------------
__global__ void zero_deg_kernel() {
    int i = blockIdx.x * blockDim.x + threadIdx.x;
    if (i < NN) g_deg[i] = 0;
}

// edge_index arrives as int32: row 0 (src) at [0,NE), row 1 (dst) at [NE,2NE)
__global__ void hist_kernel(const int* __restrict__ ei) {
    int e = blockIdx.x * blockDim.x + threadIdx.x;
    if (e < NE) {
        unsigned d = (unsigned)ei[NE + e];
        if (d < NN) atomicAdd(&g_deg[d], 1);
    }
}

// single-block scan: 1024 threads, each owns 40 contiguous nodes, two passes
__global__ void scan_kernel() {
    const int PER = 40;  // 1024*40 = 40960 >= NN
    int tid = threadIdx.x;
    int lane = tid & 31, w = tid >> 5;
    int base = tid * PER;

    int total = 0;
    for (int j = 0; j < PER; j++) {
        int i = base + j;
        if (i < NN) total += g_deg[i];
    }
    // block exclusive scan of per-thread totals
    int incl = total;
    #pragma unroll
    for (int off = 1; off < 32; off <<= 1) {
        int t = __shfl_up_sync(0xFFFFFFFFu, incl, off);
        if (lane >= off) incl += t;
    }
    __shared__ int wsum[32];
    if (lane == 31) wsum[w] = incl;
    __syncthreads();
    if (w == 0) {
        int v = wsum[lane];
        #pragma unroll
        for (int off = 1; off < 32; off <<= 1) {
            int t = __shfl_up_sync(0xFFFFFFFFu, v, off);
            if (lane >= off) v += t;
        }
        wsum[lane] = v;
    }
    __syncthreads();
    int run = incl - total + (w > 0 ? wsum[w - 1] : 0);  // exclusive prefix
    for (int j = 0; j < PER; j++) {
        int i = base + j;
        if (i < NN) {
            int v = g_deg[i];
            g_rowptr[i] = run;
            g_cursor[i] = run;
            g_invdeg[i] = 1.0f / (float)(v > 1 ? v : 1);
            run += v;
        }
    }
    if (tid == 1023) g_rowptr[NN] = run;
}

__global__ void fill_kernel(const int* __restrict__ ei) {
    int e = blockIdx.x * blockDim.x + threadIdx.x;
    if (e < NE) {
        unsigned dst = (unsigned)ei[NE + e];
        unsigned src = (unsigned)ei[e];
        if (dst < NN && src < NN) {
            int pos = atomicAdd(&g_cursor[dst], 1);
            g_esrc[pos] = (int)src;
        }
    }
}

// ---------------- edge aggregation: one warp per node ----------------
// agg[i] = inv_deg[i] * sum_{e in seg(i)} relu(A[i] + B[src_e])
__global__ void agg_kernel() {
    int gt = blockIdx.x * blockDim.x + threadIdx.x;
    int node = gt >> 5;
    int lane = threadIdx.x & 31;
    if (node >= NN) return;
    int c = lane << 2;
    const float4 a = *(const float4*)&g_A[node * DD + c];
    float4 acc = make_float4(0.f, 0.f, 0.f, 0.f);
    int e0 = g_rowptr[node];
    int e1 = g_rowptr[node + 1];
    for (int e = e0; e < e1; ++e) {
        int s = g_esrc[e];
        float4 b = *(const float4*)&g_B[s * DD + c];
        acc.x += fmaxf(a.x + b.x, 0.f);
        acc.y += fmaxf(a.y + b.y, 0.f);
        acc.z += fmaxf(a.z + b.z, 0.f);
        acc.w += fmaxf(a.w + b.w, 0.f);
    }
    float id = g_invdeg[node];
    float4 o = make_float4(acc.x * id, acc.y * id, acc.z * id, acc.w * id);
    *(float4*)&g_agg[node * DD + c] = o;
}

// ---------------- tf32 tensor-core GEMM --------------------------------------
// out[m, 0:128] = f( sum_s X_s @ W_s + bias ) (+ res)
// X: [M,128] fp32 row-major, W: [128,128] fp32 row-major.
// BM=BN=128, KB=32. 256 threads = 8 warps in 4x2 (M x N); warp tile 32x64.
// mma.sync.m16n8k8 tf32: per warp 2 Mfrags x 8 Nfrags.
template <int NSRC, bool RELU, bool RES, bool HASBIAS>
__global__ void __launch_bounds__(256) mma_gemm_kernel(
    const float* __restrict__ Xext, const float* __restrict__ W1,
    const float* __restrict__ W2, const float* __restrict__ bias,
    float* __restrict__ OutExt,
    int x1_id, int x2_id, int res_id, int out_id) {
    __shared__ uint32_t Xs[128][36];   // pad 36: A-frag LDS conflict-free
    __shared__ uint32_t Ws[32][136];   // pad 136: B-frag LDS conflict-free

    const float* X1 = (x1_id < 0) ? Xext : resolve_buf(x1_id);
    const float* X2 = (NSRC == 2) ? resolve_buf(x2_id) : nullptr;
    const float* res = RES ? ((res_id < 0) ? Xext : resolve_buf(res_id)) : nullptr;
    float* out = (out_id < 0) ? OutExt : resolve_buf(out_id);

    int tid = threadIdx.x;
    int lane = tid & 31;
    int wid = tid >> 5;
    int warp_m = wid >> 1;          // 0..3
    int warp_n = wid & 1;           // 0..1
    int m0 = blockIdx.x * 128;
    int g = lane >> 2;              // groupID 0..7
    int tg = lane & 3;              // threadID_in_group 0..3

    float C[2][8][4];
    #pragma unroll
    for (int i = 0; i < 2; i++)
        #pragma unroll
        for (int j = 0; j < 8; j++)
            #pragma unroll
            for (int k = 0; k < 4; k++) C[i][j][k] = 0.f;

    #pragma unroll
    for (int s = 0; s < NSRC; s++) {
        const float* X = (s == 0) ? X1 : X2;
        const float* W = (s == 0) ? W1 : W2;
        for (int k0 = 0; k0 < 128; k0 += 32) {
            __syncthreads();
            // X chunk [128 x 32] -> Xs (tf32-converted)
            #pragma unroll
            for (int i = 0; i < 4; i++) {
                int f = tid + i * 256;          // 0..1023
                int row = f >> 3;               // 0..127
                int kq = (f & 7) << 2;          // 0..28 step 4
                int m = m0 + row;
                float4 v = make_float4(0.f, 0.f, 0.f, 0.f);
                if (m < NN) v = *(const float4*)&X[m * 128 + k0 + kq];
                uint4 u = make_uint4(f2tf32(v.x), f2tf32(v.y), f2tf32(v.z), f2tf32(v.w));
                *(uint4*)&Xs[row][kq] = u;
            }
            // W chunk [32 x 128] -> Ws (tf32-converted)
            #pragma unroll
            for (int i = 0; i < 4; i++) {
                int f = tid + i * 256;
                int kr = f >> 5;                // 0..31
                int col = (f & 31) << 2;        // 0..124 step 4
                float4 v = *(const float4*)&W[(k0 + kr) * 128 + col];
                uint4 u = make_uint4(f2tf32(v.x), f2tf32(v.y), f2tf32(v.z), f2tf32(v.w));
                *(uint4*)&Ws[kr][col] = u;
            }
            __syncthreads();
            #pragma unroll
            for (int kk = 0; kk < 32; kk += 8) {
                uint32_t a[2][4];
                #pragma unroll
                for (int mf = 0; mf < 2; mf++) {
                    int r = warp_m * 32 + mf * 16 + g;
                    int cb = kk + tg;
                    a[mf][0] = Xs[r][cb];
                    a[mf][1] = Xs[r + 8][cb];
                    a[mf][2] = Xs[r][cb + 4];
                    a[mf][3] = Xs[r + 8][cb + 4];
                }
                #pragma unroll
                for (int nf = 0; nf < 8; nf++) {
                    int col = warp_n * 64 + nf * 8 + g;
                    uint32_t b0 = Ws[kk + tg][col];
                    uint32_t b1 = Ws[kk + tg + 4][col];
                    #pragma unroll
                    for (int mf = 0; mf < 2; mf++) {
                        asm volatile(
                            "mma.sync.aligned.m16n8k8.row.col.f32.tf32.tf32.f32 "
                            "{%0,%1,%2,%3}, {%4,%5,%6,%7}, {%8,%9}, {%0,%1,%2,%3};"
                            : "+f"(C[mf][nf][0]), "+f"(C[mf][nf][1]),
                              "+f"(C[mf][nf][2]), "+f"(C[mf][nf][3])
                            : "r"(a[mf][0]), "r"(a[mf][1]), "r"(a[mf][2]), "r"(a[mf][3]),
                              "r"(b0), "r"(b1));
                    }
                }
            }
        }
    }

    // epilogue
    #pragma unroll
    for (int nf = 0; nf < 8; nf++) {
        int col = warp_n * 64 + nf * 8 + tg * 2;
        float b0 = 0.f, b1 = 0.f;
        if (HASBIAS) { b0 = bias[col]; b1 = bias[col + 1]; }
        #pragma unroll
        for (int mf = 0; mf < 2; mf++) {
            #pragma unroll
            for (int h = 0; h < 2; h++) {       // h=0: rows g, h=1: rows g+8
                int m = m0 + warp_m * 32 + mf * 16 + g + h * 8;
                if (m >= NN) continue;
                float v0 = C[mf][nf][h * 2 + 0] + b0;
                float v1 = C[mf][nf][h * 2 + 1] + b1;
                if (RELU) { v0 = fmaxf(v0, 0.f); v1 = fmaxf(v1, 0.f); }
                if (RES) {
                    float2 r = *(const float2*)&res[m * 128 + col];
                    v0 += r.x; v1 += r.y;
                }
                *(float2*)&out[m * 128 + col] = make_float2(v0, v1);
            }
        }
    }
}

// ---------------- launch ----------------
extern "C" void kernel_launch(void* const* d_in, const int* in_sizes, int n_in,
                              void* d_out, int out_size) {
    const float* x     = (const float*)d_in[0];
    const int*   ei    = (const int*)d_in[1];     // int64 -> int32 by harness
    const float* psi_w = (const float*)d_in[2];
    const float* psi_b = (const float*)d_in[3];
    const float* phi_w = (const float*)d_in[4];
    const float* phi_b = (const float*)d_in[5];
    const float* dp_w  = (const float*)d_in[6];
    const float* dp_b  = (const float*)d_in[7];
    float* out = (float*)d_out;

    zero_deg_kernel<<<(NN + 255) / 256, 256>>>();
    hist_kernel<<<(NE + 255) / 256, 256>>>(ei);
    scan_kernel<<<1, 1024>>>();
    fill_kernel<<<(NE + 255) / 256, 256>>>(ei);

    const int GB = (NN + 127) / 128;          // 313 blocks
    const int AGG_BLOCKS = (NN * 32 + 255) / 256;

    // buffer ids: 0=g_A 1=g_B 2=g_agg 3=g_xa 4=g_xb, -1=external
    int xin_id = -1;
    for (int l = 0; l < LL; l++) {
        const float* psiT = psi_w + (size_t)l * 256 * 128;   // top half
        const float* psiB = psiT + 128 * 128;                // bottom half
        // A = x @ psi_top + psi_b ; B = x @ psi_bot
        mma_gemm_kernel<1, false, false, true><<<GB, 256>>>(
            x, psiT, nullptr, psi_b + (size_t)l * 128, nullptr,
            xin_id, -1, -1, 0);
        mma_gemm_kernel<1, false, false, false><<<GB, 256>>>(
            x, psiB, nullptr, nullptr, nullptr,
            xin_id, -1, -1, 1);
        // agg = scatter-mean(relu(A[dst] + B[src]))
        agg_kernel<<<AGG_BLOCKS, 256>>>();
        // x = relu(x @ phi_top + agg @ phi_bot + phi_b) + x
        const float* phiT = phi_w + (size_t)l * 256 * 128;
        const float* phiB = phiT + 128 * 128;
        int xout_id = 3 + (l & 1);
        mma_gemm_kernel<2, true, true, true><<<GB, 256>>>(
            x, phiT, phiB, phi_b + (size_t)l * 128, nullptr,
            xin_id, 2, xin_id, xout_id);
        xin_id = xout_id;
    }
    // out = x @ dp_w + dp_b
    mma_gemm_kernel<1, false, false, true><<<GB, 256>>>(
        x, dp_w, nullptr, dp_b, out,
        xin_id, -1, -1, -1);
}

// round 6
// speedup vs baseline: 1.7474x; 1.0240x over previous
#include <cuda_runtime.h>
#include <cstdint>

#define NN 40000
#define NE 640000
#define DD 128
#define LL 3

// ---------------- scratch (static __device__, no allocation) ----------------
__device__ __align__(256) float g_A[NN * DD];    // x @ psi_top + psi_b (by dst)
__device__ __align__(256) float g_B[NN * DD];    // x @ psi_bot        (by src)
__device__ __align__(256) float g_agg[NN * DD];  // scatter-mean result
__device__ __align__(256) float g_xa[NN * DD];   // x double buffer 0
__device__ __align__(256) float g_xb[NN * DD];   // x double buffer 1
__device__ float g_invdeg[NN];
__device__ int   g_deg[NN];
__device__ int   g_rowptr[NN + 1];
__device__ int   g_cursor[NN];
__device__ int   g_esrc[NE];        // CSR: source node per edge, grouped by dst

__device__ __forceinline__ float* resolve_buf(int id) {
    switch (id) {
        case 0: return g_A;
        case 1: return g_B;
        case 2: return g_agg;
        case 3: return g_xa;
        case 4: return g_xb;
        default: return nullptr;
    }
}

__device__ __forceinline__ uint32_t f2tf32(float f) {
    uint32_t u;
    asm("cvt.rna.tf32.f32 %0, %1;" : "=r"(u) : "f"(f));
    return u;
}

// ---------------- CSR build ----------------
__global__ void zero_deg_kernel() {
    int i = blockIdx.x * blockDim.x + threadIdx.x;
    if (i < NN) g_deg[i] = 0;
}

// edge_index arrives as int32: row 0 (src) at [0,NE), row 1 (dst) at [NE,2NE)
__global__ void hist_kernel(const int* __restrict__ ei) {
    int e = blockIdx.x * blockDim.x + threadIdx.x;
    if (e < NE) {
        unsigned d = (unsigned)ei[NE + e];
        if (d < NN) atomicAdd(&g_deg[d], 1);
    }
}

// single-block scan: 1024 threads, each owns 40 contiguous nodes, two passes
__global__ void scan_kernel() {
    const int PER = 40;  // 1024*40 = 40960 >= NN
    int tid = threadIdx.x;
    int lane = tid & 31, w = tid >> 5;
    int base = tid * PER;

    int total = 0;
    for (int j = 0; j < PER; j++) {
        int i = base + j;
        if (i < NN) total += g_deg[i];
    }
    int incl = total;
    #pragma unroll
    for (int off = 1; off < 32; off <<= 1) {
        int t = __shfl_up_sync(0xFFFFFFFFu, incl, off);
        if (lane >= off) incl += t;
    }
    __shared__ int wsum[32];
    if (lane == 31) wsum[w] = incl;
    __syncthreads();
    if (w == 0) {
        int v = wsum[lane];
        #pragma unroll
        for (int off = 1; off < 32; off <<= 1) {
            int t = __shfl_up_sync(0xFFFFFFFFu, v, off);
            if (lane >= off) v += t;
        }
        wsum[lane] = v;
    }
    __syncthreads();
    int run = incl - total + (w > 0 ? wsum[w - 1] : 0);
    for (int j = 0; j < PER; j++) {
        int i = base + j;
        if (i < NN) {
            int v = g_deg[i];
            g_rowptr[i] = run;
            g_cursor[i] = run;
            g_invdeg[i] = 1.0f / (float)(v > 1 ? v : 1);
            run += v;
        }
    }
    if (tid == 1023) g_rowptr[NN] = run;
}

__global__ void fill_kernel(const int* __restrict__ ei) {
    int e = blockIdx.x * blockDim.x + threadIdx.x;
    if (e < NE) {
        unsigned dst = (unsigned)ei[NE + e];
        unsigned src = (unsigned)ei[e];
        if (dst < NN && src < NN) {
            int pos = atomicAdd(&g_cursor[dst], 1);
            g_esrc[pos] = (int)src;
        }
    }
}

// ---------------- edge aggregation: one warp per node ----------------
// agg[i] = inv_deg[i] * sum_{e in seg(i)} relu(A[i] + B[src_e])
__global__ void agg_kernel() {
    int gt = blockIdx.x * blockDim.x + threadIdx.x;
    int node = gt >> 5;
    int lane = threadIdx.x & 31;
    if (node >= NN) return;
    int c = lane << 2;
    const float4 a = *(const float4*)&g_A[node * DD + c];
    float4 acc = make_float4(0.f, 0.f, 0.f, 0.f);
    int e0 = g_rowptr[node];
    int e1 = g_rowptr[node + 1];
    for (int e = e0; e < e1; ++e) {
        int s = g_esrc[e];
        float4 b = *(const float4*)&g_B[s * DD + c];
        acc.x += fmaxf(a.x + b.x, 0.f);
        acc.y += fmaxf(a.y + b.y, 0.f);
        acc.z += fmaxf(a.z + b.z, 0.f);
        acc.w += fmaxf(a.w + b.w, 0.f);
    }
    float id = g_invdeg[node];
    float4 o = make_float4(acc.x * id, acc.y * id, acc.z * id, acc.w * id);
    *(float4*)&g_agg[node * DD + c] = o;
}

// ---------------- fused psi GEMM: [A | B] = X @ [W1 | W2] -------------------
// BM=64, BN=256, KB=32, grid = NN/64 = 625 (exact, no bounds checks).
// 256 threads = 8 warps in 2x4 (M x N), warp tile 32x64.
// A (cols 0..127) gets biasA; B (cols 128..255) no bias.
__global__ void __launch_bounds__(256) psi_gemm_kernel(
    const float* __restrict__ Xext, const float* __restrict__ W1,
    const float* __restrict__ W2, const float* __restrict__ biasA,
    int x_id) {
    __shared__ uint32_t Xs[64][36];     // tf32, pad 36 -> conflict-free frags
    __shared__ uint32_t Ws[32][264];    // tf32, pad 264 -> conflict-free frags

    const float* X = (x_id < 0) ? Xext : resolve_buf(x_id);

    int tid = threadIdx.x;
    int lane = tid & 31;
    int wid = tid >> 5;
    int warp_m = wid >> 2;          // 0..1
    int warp_n = wid & 3;           // 0..3
    int m0 = blockIdx.x * 64;
    int g = lane >> 2;              // 0..7
    int tg = lane & 3;              // 0..3

    float C[2][8][4];
    #pragma unroll
    for (int i = 0; i < 2; i++)
        #pragma unroll
        for (int j = 0; j < 8; j++)
            #pragma unroll
            for (int k = 0; k < 4; k++) C[i][j][k] = 0.f;

    for (int k0 = 0; k0 < 128; k0 += 32) {
        __syncthreads();
        // X chunk [64 x 32]: 2048 elems, 2 float4/thread
        #pragma unroll
        for (int i = 0; i < 2; i++) {
            int f = tid + i * 256;          // 0..511
            int row = f >> 3;               // 0..63
            int kq = (f & 7) << 2;          // 0..28
            float4 v = *(const float4*)&X[(m0 + row) * 128 + k0 + kq];
            uint4 u = make_uint4(f2tf32(v.x), f2tf32(v.y), f2tf32(v.z), f2tf32(v.w));
            *(uint4*)&Xs[row][kq] = u;
        }
        // W chunk [32 x 256] from W1 (cols 0..127) and W2 (cols 128..255)
        #pragma unroll
        for (int i = 0; i < 8; i++) {
            int f = tid + i * 256;          // 0..2047
            int kr = f >> 6;                // 0..31
            int col = (f & 63) << 2;        // 0..252
            float4 v;
            if (col < 128) v = *(const float4*)&W1[(k0 + kr) * 128 + col];
            else           v = *(const float4*)&W2[(k0 + kr) * 128 + (col - 128)];
            uint4 u = make_uint4(f2tf32(v.x), f2tf32(v.y), f2tf32(v.z), f2tf32(v.w));
            *(uint4*)&Ws[kr][col] = u;
        }
        __syncthreads();
        #pragma unroll
        for (int kk = 0; kk < 32; kk += 8) {
            uint32_t a[2][4];
            #pragma unroll
            for (int mf = 0; mf < 2; mf++) {
                int r = warp_m * 32 + mf * 16 + g;
                int cb = kk + tg;
                a[mf][0] = Xs[r][cb];
                a[mf][1] = Xs[r + 8][cb];
                a[mf][2] = Xs[r][cb + 4];
                a[mf][3] = Xs[r + 8][cb + 4];
            }
            #pragma unroll
            for (int nf = 0; nf < 8; nf++) {
                int col = warp_n * 64 + nf * 8 + g;
                uint32_t b0 = Ws[kk + tg][col];
                uint32_t b1 = Ws[kk + tg + 4][col];
                #pragma unroll
                for (int mf = 0; mf < 2; mf++) {
                    asm volatile(
                        "mma.sync.aligned.m16n8k8.row.col.f32.tf32.tf32.f32 "
                        "{%0,%1,%2,%3}, {%4,%5,%6,%7}, {%8,%9}, {%0,%1,%2,%3};"
                        : "+f"(C[mf][nf][0]), "+f"(C[mf][nf][1]),
                          "+f"(C[mf][nf][2]), "+f"(C[mf][nf][3])
                        : "r"(a[mf][0]), "r"(a[mf][1]), "r"(a[mf][2]), "r"(a[mf][3]),
                          "r"(b0), "r"(b1));
                }
            }
        }
    }

    // epilogue: cols < 128 -> g_A (+bias); cols >= 128 -> g_B
    #pragma unroll
    for (int nf = 0; nf < 8; nf++) {
        int col = warp_n * 64 + nf * 8 + tg * 2;
        float* outp;
        float b0, b1;
        if (col < 128) {
            outp = g_A;
            b0 = biasA[col]; b1 = biasA[col + 1];
        } else {
            outp = g_B;
            col -= 128;
            b0 = 0.f; b1 = 0.f;
        }
        #pragma unroll
        for (int mf = 0; mf < 2; mf++) {
            #pragma unroll
            for (int h = 0; h < 2; h++) {
                int m = m0 + warp_m * 32 + mf * 16 + g + h * 8;
                float v0 = C[mf][nf][h * 2 + 0] + b0;
                float v1 = C[mf][nf][h * 2 + 1] + b1;
                *(float2*)&outp[m * 128 + col] = make_float2(v0, v1);
            }
        }
    }
}

// ---------------- tf32 GEMM (phi / dp): out = f(sum_s X_s@W_s + bias)(+res) -
// BM=BN=128, KB=32, 256 threads = 8 warps 4x2, warp tile 32x64.
template <int NSRC, bool RELU, bool RES, bool HASBIAS>
__global__ void __launch_bounds__(256) mma_gemm_kernel(
    const float* __restrict__ Xext, const float* __restrict__ W1,
    const float* __restrict__ W2, const float* __restrict__ bias,
    float* __restrict__ OutExt,
    int x1_id, int x2_id, int res_id, int out_id) {
    __shared__ uint32_t Xs[128][36];
    __shared__ uint32_t Ws[32][136];

    const float* X1 = (x1_id < 0) ? Xext : resolve_buf(x1_id);
    const float* X2 = (NSRC == 2) ? resolve_buf(x2_id) : nullptr;
    const float* res = RES ? ((res_id < 0) ? Xext : resolve_buf(res_id)) : nullptr;
    float* out = (out_id < 0) ? OutExt : resolve_buf(out_id);

    int tid = threadIdx.x;
    int lane = tid & 31;
    int wid = tid >> 5;
    int warp_m = wid >> 1;          // 0..3
    int warp_n = wid & 1;           // 0..1
    int m0 = blockIdx.x * 128;
    int g = lane >> 2;
    int tg = lane & 3;

    float C[2][8][4];
    #pragma unroll
    for (int i = 0; i < 2; i++)
        #pragma unroll
        for (int j = 0; j < 8; j++)
            #pragma unroll
            for (int k = 0; k < 4; k++) C[i][j][k] = 0.f;

    #pragma unroll
    for (int s = 0; s < NSRC; s++) {
        const float* X = (s == 0) ? X1 : X2;
        const float* W = (s == 0) ? W1 : W2;
        for (int k0 = 0; k0 < 128; k0 += 32) {
            __syncthreads();
            #pragma unroll
            for (int i = 0; i < 4; i++) {
                int f = tid + i * 256;          // 0..1023
                int row = f >> 3;               // 0..127
                int kq = (f & 7) << 2;          // 0..28
                int m = m0 + row;
                float4 v = make_float4(0.f, 0.f, 0.f, 0.f);
                if (m < NN) v = *(const float4*)&X[m * 128 + k0 + kq];
                uint4 u = make_uint4(f2tf32(v.x), f2tf32(v.y), f2tf32(v.z), f2tf32(v.w));
                *(uint4*)&Xs[row][kq] = u;
            }
            #pragma unroll
            for (int i = 0; i < 4; i++) {
                int f = tid + i * 256;
                int kr = f >> 5;                // 0..31
                int col = (f & 31) << 2;        // 0..124
                float4 v = *(const float4*)&W[(k0 + kr) * 128 + col];
                uint4 u = make_uint4(f2tf32(v.x), f2tf32(v.y), f2tf32(v.z), f2tf32(v.w));
                *(uint4*)&Ws[kr][col] = u;
            }
            __syncthreads();
            #pragma unroll
            for (int kk = 0; kk < 32; kk += 8) {
                uint32_t a[2][4];
                #pragma unroll
                for (int mf = 0; mf < 2; mf++) {
                    int r = warp_m * 32 + mf * 16 + g;
                    int cb = kk + tg;
                    a[mf][0] = Xs[r][cb];
                    a[mf][1] = Xs[r + 8][cb];
                    a[mf][2] = Xs[r][cb + 4];
                    a[mf][3] = Xs[r + 8][cb + 4];
                }
                #pragma unroll
                for (int nf = 0; nf < 8; nf++) {
                    int col = warp_n * 64 + nf * 8 + g;
                    uint32_t b0 = Ws[kk + tg][col];
                    uint32_t b1 = Ws[kk + tg + 4][col];
                    #pragma unroll
                    for (int mf = 0; mf < 2; mf++) {
                        asm volatile(
                            "mma.sync.aligned.m16n8k8.row.col.f32.tf32.tf32.f32 "
                            "{%0,%1,%2,%3}, {%4,%5,%6,%7}, {%8,%9}, {%0,%1,%2,%3};"
                            : "+f"(C[mf][nf][0]), "+f"(C[mf][nf][1]),
                              "+f"(C[mf][nf][2]), "+f"(C[mf][nf][3])
                            : "r"(a[mf][0]), "r"(a[mf][1]), "r"(a[mf][2]), "r"(a[mf][3]),
                              "r"(b0), "r"(b1));
                    }
                }
            }
        }
    }

    #pragma unroll
    for (int nf = 0; nf < 8; nf++) {
        int col = warp_n * 64 + nf * 8 + tg * 2;
        float b0 = 0.f, b1 = 0.f;
        if (HASBIAS) { b0 = bias[col]; b1 = bias[col + 1]; }
        #pragma unroll
        for (int mf = 0; mf < 2; mf++) {
            #pragma unroll
            for (int h = 0; h < 2; h++) {
                int m = m0 + warp_m * 32 + mf * 16 + g + h * 8;
                if (m >= NN) continue;
                float v0 = C[mf][nf][h * 2 + 0] + b0;
                float v1 = C[mf][nf][h * 2 + 1] + b1;
                if (RELU) { v0 = fmaxf(v0, 0.f); v1 = fmaxf(v1, 0.f); }
                if (RES) {
                    float2 r = *(const float2*)&res[m * 128 + col];
                    v0 += r.x; v1 += r.y;
                }
                *(float2*)&out[m * 128 + col] = make_float2(v0, v1);
            }
        }
    }
}

// ---------------- launch ----------------
extern "C" void kernel_launch(void* const* d_in, const int* in_sizes, int n_in,
                              void* d_out, int out_size) {
    const float* x     = (const float*)d_in[0];
    const int*   ei    = (const int*)d_in[1];     // int64 -> int32 by harness
    const float* psi_w = (const float*)d_in[2];
    const float* psi_b = (const float*)d_in[3];
    const float* phi_w = (const float*)d_in[4];
    const float* phi_b = (const float*)d_in[5];
    const float* dp_w  = (const float*)d_in[6];
    const float* dp_b  = (const float*)d_in[7];
    float* out = (float*)d_out;

    zero_deg_kernel<<<(NN + 255) / 256, 256>>>();
    hist_kernel<<<(NE + 255) / 256, 256>>>(ei);
    scan_kernel<<<1, 1024>>>();
    fill_kernel<<<(NE + 255) / 256, 256>>>(ei);

    const int GB128 = (NN + 127) / 128;       // 313
    const int GB64  = NN / 64;                // 625 exact
    const int AGG_BLOCKS = (NN * 32 + 255) / 256;

    // buffer ids: 0=g_A 1=g_B 2=g_agg 3=g_xa 4=g_xb, -1=external
    int xin_id = -1;
    for (int l = 0; l < LL; l++) {
        const float* psiT = psi_w + (size_t)l * 256 * 128;   // top half
        const float* psiB = psiT + 128 * 128;                // bottom half
        // [A|B] = x @ [psi_top | psi_bot], A += psi_b
        psi_gemm_kernel<<<GB64, 256>>>(x, psiT, psiB,
                                       psi_b + (size_t)l * 128, xin_id);
        // agg = scatter-mean(relu(A[dst] + B[src]))
        agg_kernel<<<AGG_BLOCKS, 256>>>();
        // x = relu(x @ phi_top + agg @ phi_bot + phi_b) + x
        const float* phiT = phi_w + (size_t)l * 256 * 128;
        const float* phiB = phiT + 128 * 128;
        int xout_id = 3 + (l & 1);
        mma_gemm_kernel<2, true, true, true><<<GB128, 256>>>(
            x, phiT, phiB, phi_b + (size_t)l * 128, nullptr,
            xin_id, 2, xin_id, xout_id);
        xin_id = xout_id;
    }
    // out = x @ dp_w + dp_b
    mma_gemm_kernel<1, false, false, true><<<GB128, 256>>>(
        x, dp_w, nullptr, dp_b, out,
        xin_id, -1, -1, -1);
}

// round 8
// speedup vs baseline: 1.7766x; 1.0167x over previous
#include <cuda_runtime.h>
#include <cstdint>

#define NN 40000
#define NE 640000
#define DD 128
#define LL 3
#define GRID 148
#define NTILES (NN / 64)          // 625 exact

// ---------------- scratch (static __device__, no allocation) ----------------
__device__ __align__(256) float g_A[NN * DD];    // x @ psi_top + psi_b (by dst)
__device__ __align__(256) float g_B[NN * DD];    // x @ psi_bot        (by src)
__device__ __align__(256) float g_agg[NN * DD];  // scatter-mean result
__device__ __align__(256) float g_xa[NN * DD];   // x double buffer 0
__device__ __align__(256) float g_xb[NN * DD];   // x double buffer 1
__device__ float g_invdeg[NN];
__device__ int   g_deg[NN];
__device__ int   g_rowptr[NN + 1];
__device__ int   g_cursor[NN];
__device__ int   g_esrc[NE];

__device__ __forceinline__ float* resolve_buf(int id) {
    switch (id) {
        case 0: return g_A;
        case 1: return g_B;
        case 2: return g_agg;
        case 3: return g_xa;
        case 4: return g_xb;
        default: return nullptr;
    }
}

__device__ __forceinline__ uint32_t f2tf32(float f) {
    uint32_t u;
    asm("cvt.rna.tf32.f32 %0, %1;" : "=r"(u) : "f"(f));
    return u;
}

#define CP16(dst_u32, src_ptr) \
    asm volatile("cp.async.cg.shared.global [%0], [%1], 16;\n" \
                 :: "r"(dst_u32), "l"(src_ptr))

// ---------------- CSR build ----------------
__global__ void zero_deg_kernel() {
    int i = blockIdx.x * blockDim.x + threadIdx.x;
    if (i < NN) g_deg[i] = 0;
}

__global__ void hist_kernel(const int* __restrict__ ei) {
    int e = blockIdx.x * blockDim.x + threadIdx.x;
    if (e < NE) {
        unsigned d = (unsigned)ei[NE + e];
        if (d < NN) atomicAdd(&g_deg[d], 1);
    }
}

__global__ void scan_kernel() {
    const int PER = 40;
    int tid = threadIdx.x;
    int lane = tid & 31, w = tid >> 5;
    int base = tid * PER;

    int total = 0;
    for (int j = 0; j < PER; j++) {
        int i = base + j;
        if (i < NN) total += g_deg[i];
    }
    int incl = total;
    #pragma unroll
    for (int off = 1; off < 32; off <<= 1) {
        int t = __shfl_up_sync(0xFFFFFFFFu, incl, off);
        if (lane >= off) incl += t;
    }
    __shared__ int wsum[32];
    if (lane == 31) wsum[w] = incl;
    __syncthreads();
    if (w == 0) {
        int v = wsum[lane];
        #pragma unroll
        for (int off = 1; off < 32; off <<= 1) {
            int t = __shfl_up_sync(0xFFFFFFFFu, v, off);
            if (lane >= off) v += t;
        }
        wsum[lane] = v;
    }
    __syncthreads();
    int run = incl - total + (w > 0 ? wsum[w - 1] : 0);
    for (int j = 0; j < PER; j++) {
        int i = base + j;
        if (i < NN) {
            int v = g_deg[i];
            g_rowptr[i] = run;
            g_cursor[i] = run;
            g_invdeg[i] = 1.0f / (float)(v > 1 ? v : 1);
            run += v;
        }
    }
    if (tid == 1023) g_rowptr[NN] = run;
}

__global__ void fill_kernel(const int* __restrict__ ei) {
    int e = blockIdx.x * blockDim.x + threadIdx.x;
    if (e < NE) {
        unsigned dst = (unsigned)ei[NE + e];
        unsigned src = (unsigned)ei[e];
        if (dst < NN && src < NN) {
            int pos = atomicAdd(&g_cursor[dst], 1);
            g_esrc[pos] = (int)src;
        }
    }
}

// ---------------- edge aggregation: one warp per node ----------------
__global__ void agg_kernel() {
    int gt = blockIdx.x * blockDim.x + threadIdx.x;
    int node = gt >> 5;
    int lane = threadIdx.x & 31;
    if (node >= NN) return;
    int c = lane << 2;
    const float4 a = *(const float4*)&g_A[node * DD + c];
    float4 acc = make_float4(0.f, 0.f, 0.f, 0.f);
    int e0 = g_rowptr[node];
    int e1 = g_rowptr[node + 1];
    for (int e = e0; e < e1; ++e) {
        int s = g_esrc[e];
        float4 b = *(const float4*)&g_B[s * DD + c];
        acc.x += fmaxf(a.x + b.x, 0.f);
        acc.y += fmaxf(a.y + b.y, 0.f);
        acc.z += fmaxf(a.z + b.z, 0.f);
        acc.w += fmaxf(a.w + b.w, 0.f);
    }
    float id = g_invdeg[node];
    float4 o = make_float4(acc.x * id, acc.y * id, acc.z * id, acc.w * id);
    *(float4*)&g_agg[node * DD + c] = o;
}

// ---------------- persistent W-resident pipelined tf32 GEMM -----------------
// PSI:  out cols [0..127] -> g_A (+biasA), [128..255] -> g_B ; W = [W1 | W2]
// else: out = f(sum_s X_s @ W_s + bias) (+res), BN=128
// Grid = GRID blocks, 512 threads (16 warps: 2 x 8). Tile BM=64.
// X streamed in 64x32 chunks through a 4-stage cp.async ring.
template <int NSRC, bool RELU, bool RES, bool HASBIAS, bool PSI>
__global__ void __launch_bounds__(512) gemm_persist(
    const float* __restrict__ Xext, const float* __restrict__ W1,
    const float* __restrict__ W2, const float* __restrict__ bias,
    float* __restrict__ OutExt,
    int x1_id, int x2_id, int res_id, int out_id)
{
    constexpr int BN = PSI ? 256 : 128;
    constexpr int WROWS = PSI ? 128 : NSRC * 128;
    constexpr int WS = BN + 8;                 // stride ≡ 8 (mod 32): conflict-free
    constexpr int NF = BN / 64;                // 4 (psi) or 2
    constexpr int NCHUNK = NSRC * 4;
    constexpr int LOG2NC = (NCHUNK == 8) ? 3 : 2;
    constexpr int XST = 64 * 36;               // floats per X stage

    extern __shared__ __align__(16) unsigned char sh_raw[];
    float*    Xsm = (float*)sh_raw;                       // [4][64][36]
    uint32_t* Wsm = (uint32_t*)(sh_raw + 4 * XST * 4);    // [WROWS][WS] tf32

    const float* X1 = (x1_id < 0) ? Xext : resolve_buf(x1_id);
    const float* X2 = (NSRC == 2) ? resolve_buf(x2_id) : nullptr;
    const float* res = RES ? ((res_id < 0) ? Xext : resolve_buf(res_id)) : nullptr;
    float* out = (out_id < 0) ? OutExt : resolve_buf(out_id);

    int tid = threadIdx.x;
    int lane = tid & 31;
    int wid = tid >> 5;
    int warp_m = wid >> 3;           // 0..1
    int warp_n = wid & 7;            // 0..7
    int g = lane >> 2;               // 0..7
    int tg = lane & 3;               // 0..3
    int b = blockIdx.x;

    uint32_t xbase;
    { uint64_t tmp = __cvta_generic_to_shared(Xsm); xbase = (uint32_t)tmp; }

    // ---- load W into smem, pre-converted to tf32 ----
    {
        constexpr int NV4 = WROWS * BN / 4 / 512;   // float4 per thread (16 or 8)
        #pragma unroll
        for (int i = 0; i < NV4; i++) {
            int f = tid + i * 512;
            int r, c;
            const float* src;
            if (PSI) {
                r = f >> 6; c = (f & 63) << 2;
                src = (c < 128) ? (W1 + r * 128 + c) : (W2 + r * 128 + (c - 128));
            } else if (NSRC == 2) {
                r = f >> 5; c = (f & 31) << 2;
                src = (r < 128) ? (W1 + r * 128 + c) : (W2 + (r - 128) * 128 + c);
            } else {
                r = f >> 5; c = (f & 31) << 2;
                src = W1 + r * 128 + c;
            }
            float4 v = *(const float4*)src;
            uint4 u = make_uint4(f2tf32(v.x), f2tf32(v.y), f2tf32(v.z), f2tf32(v.w));
            *(uint4*)&Wsm[r * WS + c] = u;
        }
    }

    // ---- bias prefetch (constant across tiles) ----
    float bv[NF][2];
    #pragma unroll
    for (int nf = 0; nf < NF; nf++) {
        int colg = warp_n * (NF * 8) + nf * 8 + tg * 2;
        bv[nf][0] = 0.f; bv[nf][1] = 0.f;
        if (PSI) {
            if (colg < 128) { bv[nf][0] = bias[colg]; bv[nf][1] = bias[colg + 1]; }
        } else if (HASBIAS) {
            bv[nf][0] = bias[colg]; bv[nf][1] = bias[colg + 1];
        }
    }

    int nt = (NTILES - b + GRID - 1) / GRID;
    int TOTAL = nt * NCHUNK;

    // per-thread X-chunk load coords
    int xrow = tid >> 3;
    int xkq = (tid & 7) << 2;

    auto issue = [&](int ci) {
        int t = b + (ci >> LOG2NC) * GRID;
        int k = ci & (NCHUNK - 1);
        const float* Xp = (NSRC == 2 && k >= 4) ? X2 : X1;
        int k0 = (k & 3) * 32;
        const float* src = Xp + (size_t)(t * 64 + xrow) * 128 + k0 + xkq;
        uint32_t dst = xbase + (((ci & 3) * XST + xrow * 36 + xkq) << 2);
        CP16(dst, src);
        asm volatile("cp.async.commit_group;\n" ::);
    };

    issue(0); issue(1); issue(2);

    float C[2][NF][4];
    #pragma unroll
    for (int i = 0; i < 2; i++)
        #pragma unroll
        for (int j = 0; j < NF; j++)
            #pragma unroll
            for (int q = 0; q < 4; q++) C[i][j][q] = 0.f;

    for (int ci = 0; ci < TOTAL; ci++) {
        int nxt = ci + 3; if (nxt > TOTAL - 1) nxt = TOTAL - 1;
        issue(nxt);
        asm volatile("cp.async.wait_group 3;\n" ::: "memory");
        __syncthreads();

        int k = ci & (NCHUNK - 1);
        int wbase = (PSI ? 0 : (k >> 2) * 128) + (k & 3) * 32;
        const float* Xst = Xsm + (ci & 3) * XST;

        #pragma unroll
        for (int kg = 0; kg < 4; kg++) {
            int kk = kg * 8;
            uint32_t a[2][4];
            #pragma unroll
            for (int mf = 0; mf < 2; mf++) {
                int r = warp_m * 32 + mf * 16 + g;
                a[mf][0] = f2tf32(Xst[r * 36 + kk + tg]);
                a[mf][1] = f2tf32(Xst[(r + 8) * 36 + kk + tg]);
                a[mf][2] = f2tf32(Xst[r * 36 + kk + tg + 4]);
                a[mf][3] = f2tf32(Xst[(r + 8) * 36 + kk + tg + 4]);
            }
            #pragma unroll
            for (int nf = 0; nf < NF; nf++) {
                int col = warp_n * (NF * 8) + nf * 8 + g;
                int wr = wbase + kk + tg;
                uint32_t b0 = Wsm[wr * WS + col];
                uint32_t b1 = Wsm[(wr + 4) * WS + col];
                #pragma unroll
                for (int mf = 0; mf < 2; mf++) {
                    asm volatile(
                        "mma.sync.aligned.m16n8k8.row.col.f32.tf32.tf32.f32 "
                        "{%0,%1,%2,%3}, {%4,%5,%6,%7}, {%8,%9}, {%0,%1,%2,%3};"
                        : "+f"(C[mf][nf][0]), "+f"(C[mf][nf][1]),
                          "+f"(C[mf][nf][2]), "+f"(C[mf][nf][3])
                        : "r"(a[mf][0]), "r"(a[mf][1]), "r"(a[mf][2]), "r"(a[mf][3]),
                          "r"(b0), "r"(b1));
                }
            }
        }

        if (k == NCHUNK - 1) {
            // epilogue for this tile
            int t = b + (ci >> LOG2NC) * GRID;
            int m0 = t * 64;
            #pragma unroll
            for (int nf = 0; nf < NF; nf++) {
                int colg = warp_n * (NF * 8) + nf * 8 + tg * 2;
                float* outp = out;
                int col = colg;
                if (PSI) {
                    if (colg < 128) outp = g_A;
                    else { outp = g_B; col = colg - 128; }
                }
                #pragma unroll
                for (int mf = 0; mf < 2; mf++) {
                    #pragma unroll
                    for (int h = 0; h < 2; h++) {
                        int m = m0 + warp_m * 32 + mf * 16 + g + h * 8;
                        float v0 = C[mf][nf][h * 2 + 0] + bv[nf][0];
                        float v1 = C[mf][nf][h * 2 + 1] + bv[nf][1];
                        if (RELU) { v0 = fmaxf(v0, 0.f); v1 = fmaxf(v1, 0.f); }
                        if (RES) {
                            float2 r = *(const float2*)&res[(size_t)m * 128 + col];
                            v0 += r.x; v1 += r.y;
                        }
                        *(float2*)&outp[(size_t)m * 128 + col] = make_float2(v0, v1);
                        C[mf][nf][h * 2 + 0] = 0.f;
                        C[mf][nf][h * 2 + 1] = 0.f;
                    }
                }
            }
        }
        __syncthreads();
    }
}

// ---------------- launch ----------------
extern "C" void kernel_launch(void* const* d_in, const int* in_sizes, int n_in,
                              void* d_out, int out_size) {
    const float* x     = (const float*)d_in[0];
    const int*   ei    = (const int*)d_in[1];
    const float* psi_w = (const float*)d_in[2];
    const float* psi_b = (const float*)d_in[3];
    const float* phi_w = (const float*)d_in[4];
    const float* phi_b = (const float*)d_in[5];
    const float* dp_w  = (const float*)d_in[6];
    const float* dp_b  = (const float*)d_in[7];
    float* out = (float*)d_out;

    // dynamic smem sizes
    const int XBYTES   = 4 * 64 * 36 * 4;                 // 36864
    const int PSI_SM   = XBYTES + 128 * 264 * 4;          // 172032
    const int PHI_SM   = XBYTES + 256 * 136 * 4;          // 176128
    const int DP_SM    = XBYTES + 128 * 136 * 4;          // 106496

    cudaFuncSetAttribute(gemm_persist<1, false, false, true, true>,
                         cudaFuncAttributeMaxDynamicSharedMemorySize, PSI_SM);
    cudaFuncSetAttribute(gemm_persist<2, true, true, true, false>,
                         cudaFuncAttributeMaxDynamicSharedMemorySize, PHI_SM);
    cudaFuncSetAttribute(gemm_persist<1, false, false, true, false>,
                         cudaFuncAttributeMaxDynamicSharedMemorySize, DP_SM);

    zero_deg_kernel<<<(NN + 255) / 256, 256>>>();
    hist_kernel<<<(NE + 255) / 256, 256>>>(ei);
    scan_kernel<<<1, 1024>>>();
    fill_kernel<<<(NE + 255) / 256, 256>>>(ei);

    const int AGG_BLOCKS = (NN * 32 + 255) / 256;

    // buffer ids: 0=g_A 1=g_B 2=g_agg 3=g_xa 4=g_xb, -1=external
    int xin_id = -1;
    for (int l = 0; l < LL; l++) {
        const float* psiT = psi_w + (size_t)l * 256 * 128;
        const float* psiB = psiT + 128 * 128;
        // [A|B] = x @ [psi_top | psi_bot], A += psi_b
        gemm_persist<1, false, false, true, true><<<GRID, 512, PSI_SM>>>(
            x, psiT, psiB, psi_b + (size_t)l * 128, nullptr,
            xin_id, -1, -1, 0);
        // agg = scatter-mean(relu(A[dst] + B[src]))
        agg_kernel<<<AGG_BLOCKS, 256>>>();
        // x = relu(x @ phi_top + agg @ phi_bot + phi_b) + x
        const float* phiT = phi_w + (size_t)l * 256 * 128;
        const float* phiB = phiT + 128 * 128;
        int xout_id = 3 + (l & 1);
        gemm_persist<2, true, true, true, false><<<GRID, 512, PHI_SM>>>(
            x, phiT, phiB, phi_b + (size_t)l * 128, nullptr,
            xin_id, 2, xin_id, xout_id);
        xin_id = xout_id;
    }
    // out = x @ dp_w + dp_b
    gemm_persist<1, false, false, true, false><<<GRID, 512, DP_SM>>>(
        x, dp_w, nullptr, dp_b, out,
        xin_id, -1, -1, -1);
}